// round 4
// baseline (speedup 1.0000x reference)
#include <cuda_runtime.h>

// Deformable Conv3d, fp32 — barrier-free warp-autonomous version.
// prep: x -> channels-last xT[b][spatial][c]; weight -> wT[k][c][o].
// deform: warp = 4 points x 64 outs, fully independent (no smem, no barriers).
//   Per k:
//     params: each lane OWNS one (point, corner) pair -> computes (byteoff, wgt) once
//     gather: 16 iters, params via shfl, coalesced 256B channel-vector LDG.128
//     GEMM:   s via shfl from sampling regs, w via direct LDG (L1-hot),
//             packed fma.rn.f32x2 over point-pairs.

namespace {
constexpr int B_    = 2;
constexpr int CIN_  = 64;
constexpr int COUT_ = 64;
constexpr int D_    = 8;
constexpr int H_    = 32;
constexpr int W_    = 32;
constexpr int K_    = 27;
constexpr int P_    = D_ * H_ * W_;   // 8192
constexpr int TP    = 32;             // points per block (8 warps x 4)
constexpr int THREADS = 256;
constexpr unsigned FULL = 0xffffffffu;
}

__device__ float g_xT[B_ * P_ * CIN_];       // [b][spatial][c]
__device__ float g_wT[K_ * CIN_ * COUT_];    // [k][c][o]

__device__ __forceinline__ unsigned long long pk2(float x, float y) {
    unsigned long long r;
    asm("mov.b64 %0, {%1, %2};" : "=l"(r) : "f"(x), "f"(y));
    return r;
}
__device__ __forceinline__ float2 upk(unsigned long long v) {
    float2 f;
    asm("mov.b64 {%0, %1}, %2;" : "=f"(f.x), "=f"(f.y) : "l"(v));
    return f;
}
__device__ __forceinline__ void ffma2(unsigned long long& d,
                                      unsigned long long a,
                                      unsigned long long b) {
    asm("fma.rn.f32x2 %0, %1, %2, %0;" : "+l"(d) : "l"(a), "l"(b));
}

__global__ void prep_kernel(const float* __restrict__ x,
                            const float* __restrict__ w) {
    int stride = gridDim.x * blockDim.x;
    int tid = blockIdx.x * blockDim.x + threadIdx.x;
    for (int i = tid; i < B_ * CIN_ * P_; i += stride) {
        int s = i % P_;
        int c = (i / P_) % CIN_;
        int b = i / (P_ * CIN_);
        g_xT[(b * P_ + s) * CIN_ + c] = x[i];
    }
    for (int i = tid; i < COUT_ * CIN_ * K_; i += stride) {
        int k = i % K_;
        int c = (i / K_) % CIN_;
        int o = i / (K_ * CIN_);
        g_wT[(k * CIN_ + c) * COUT_ + o] = w[i];
    }
}

__global__ __launch_bounds__(THREADS)
void deform_kernel(const float* __restrict__ offset,
                   const float* __restrict__ bias,
                   float* __restrict__ out) {
    const int tid  = threadIdx.x;
    const int lane = tid & 31;
    const int warp = tid >> 5;
    const int blk  = blockIdx.x;
    const int b    = blk >> 8;
    const int p0   = (blk & 255) * TP;

    const float* offB = offset + (size_t)b * 3 * K_ * P_;
    const char*  xTbB = reinterpret_cast<const char*>(g_xT + (size_t)b * P_ * CIN_);

    const int plb = warp * 4;            // warp's 4 points: p0+plb .. +3
    const int pb  = p0 + plb;

    // ---- this lane's owned (point, corner) pair ----
    const int i_own  = (lane >> 2) & 3;          // point index 0..3
    const int jj_own = lane & 3;                 // corner slot within half
    const int h_own  = lane >> 4;                // half
    const int j_own  = jj_own * 2 + h_own;       // corner 0..7
    const int dd = (j_own >> 2) & 1, dh = (j_own >> 1) & 1, dw = j_own & 1;

    const int p_own  = pb + i_own;
    const int od = p_own >> 10;
    const int oh = (p_own >> 5) & 31;
    const int ow = p_own & 31;

    const int half = lane >> 4;                  // gather role
    const int c4   = lane & 15;

    unsigned long long acc00 = 0ull, acc01 = 0ull;   // out o0: (p0,p1),(p2,p3)
    unsigned long long acc10 = 0ull, acc11 = 0ull;   // out o1

    const float* wkbase = g_wT;

    for (int k = 0; k < K_; k++) {
        const int kd = k / 9, kh = (k / 3) % 3, kw = k % 3;

        // ---- params: one (point,corner) per lane ----
        const float* offk = offB + 3 * k * P_;
        float zd = (float)(od - 1 + kd) + __ldg(&offk[0 * P_ + p_own]);
        float zh = (float)(oh - 1 + kh) + __ldg(&offk[1 * P_ + p_own]);
        float zw = (float)(ow - 1 + kw) + __ldg(&offk[2 * P_ + p_own]);
        float fd = floorf(zd), fh = floorf(zh), fw = floorf(zw);
        int d0 = (int)fd, h0 = (int)fh, w0 = (int)fw;
        float rd = zd - fd, rh = zh - fh, rw = zw - fw;

        int di = d0 + dd, hi = h0 + dh, wi = w0 + dw;
        bool valid = (di >= 0) & (di < D_) & (hi >= 0) & (hi < H_) &
                     (wi >= 0) & (wi < W_);
        float wgt = (dd ? rd : 1.f - rd) * (dh ? rh : 1.f - rh) *
                    (dw ? rw : 1.f - rw);
        wgt = valid ? wgt : 0.f;
        int dic = min(max(di, 0), D_ - 1);
        int hic = min(max(hi, 0), H_ - 1);
        int wic = min(max(wi, 0), W_ - 1);
        int bo = (((dic * H_ + hic) * W_ + wic) * CIN_) * 4;  // byte offset

        // ---- gather: all lanes fetch channel chunk c4 for (point i2, its half's corners) ----
        float4 a[4];
#pragma unroll
        for (int i2 = 0; i2 < 4; i2++) a[i2] = make_float4(0.f, 0.f, 0.f, 0.f);

#pragma unroll
        for (int i2 = 0; i2 < 4; i2++) {
#pragma unroll
            for (int jj2 = 0; jj2 < 4; jj2++) {
                int src = (lane & 16) | (i2 * 4 + jj2);
                int   bos = __shfl_sync(FULL, bo, src);
                float wgs = __shfl_sync(FULL, wgt, src);
                float4 v = __ldg(reinterpret_cast<const float4*>(
                                     xTbB + bos + (c4 << 4)));
                a[i2].x += wgs * v.x; a[i2].y += wgs * v.y;
                a[i2].z += wgs * v.z; a[i2].w += wgs * v.w;
            }
        }
        // combine halves -> lanes 0..15 hold final s[point][c4*4..+3]
#pragma unroll
        for (int i2 = 0; i2 < 4; i2++) {
            a[i2].x += __shfl_down_sync(FULL, a[i2].x, 16);
            a[i2].y += __shfl_down_sync(FULL, a[i2].y, 16);
            a[i2].z += __shfl_down_sync(FULL, a[i2].z, 16);
            a[i2].w += __shfl_down_sync(FULL, a[i2].w, 16);
        }

        // ---- GEMM: lane = out pair (lane, lane+32), packed over point pairs ----
        const float* wk = wkbase + k * (CIN_ * COUT_);
#pragma unroll
        for (int q = 0; q < 16; q++) {
#pragma unroll
            for (int r = 0; r < 4; r++) {
                const int c = q * 4 + r;
                float s0 = __shfl_sync(FULL, (&a[0].x)[r], q);
                float s1 = __shfl_sync(FULL, (&a[1].x)[r], q);
                float s2 = __shfl_sync(FULL, (&a[2].x)[r], q);
                float s3 = __shfl_sync(FULL, (&a[3].x)[r], q);
                unsigned long long s01 = pk2(s0, s1);
                unsigned long long s23 = pk2(s2, s3);
                float w0 = __ldg(&wk[c * COUT_ + lane]);
                float w1 = __ldg(&wk[c * COUT_ + lane + 32]);
                unsigned long long w0p = pk2(w0, w0);
                unsigned long long w1p = pk2(w1, w1);
                ffma2(acc00, w0p, s01);
                ffma2(acc01, w0p, s23);
                ffma2(acc10, w1p, s01);
                ffma2(acc11, w1p, s23);
            }
        }
    }

    // ---- epilogue ----
    const float b0 = __ldg(&bias[lane]);
    const float b1 = __ldg(&bias[lane + 32]);
    float2 r00 = upk(acc00), r01 = upk(acc01);
    float2 r10 = upk(acc10), r11 = upk(acc11);
    r00.x += b0; r00.y += b0; r01.x += b0; r01.y += b0;
    r10.x += b1; r10.y += b1; r11.x += b1; r11.y += b1;

    float* row0 = out + ((size_t)b * COUT_ + lane) * P_ + pb;
    float* row1 = out + ((size_t)b * COUT_ + lane + 32) * P_ + pb;
    *reinterpret_cast<float2*>(row0)     = r00;
    *reinterpret_cast<float2*>(row0 + 2) = r01;
    *reinterpret_cast<float2*>(row1)     = r10;
    *reinterpret_cast<float2*>(row1 + 2) = r11;
}

extern "C" void kernel_launch(void* const* d_in, const int* in_sizes, int n_in,
                              void* d_out, int out_size) {
    const float* x      = (const float*)d_in[0];
    const float* offset = (const float*)d_in[1];
    const float* weight = (const float*)d_in[2];
    const float* bias   = (const float*)d_in[3];
    float* out = (float*)d_out;

    prep_kernel<<<256, THREADS>>>(x, weight);
    deform_kernel<<<B_ * (P_ / TP), THREADS>>>(offset, bias, out);
}

// round 6
// speedup vs baseline: 2.3845x; 2.3845x over previous
#include <cuda_runtime.h>
#include <cuda_bf16.h>
#include <cstdint>

// Deformable Conv3d via portable HMMA (mma.sync.m16n8k16.bf16, hi/lo split).
// prep:  x -> channels-last fp32 xT[b][p][c];
//        weight -> per-tap SW128-swizzled bf16 hi/lo SMEM images (global).
// main:  block = 128 points x 64 outs, 512 thr (16 warps).
//   Per tap k: all warps sample 8 points each (factored trilinear, coalesced
//   256B channel vectors), split bf16 hi/lo -> swizzled SMEM A tile; stage
//   pre-swizzled weight tile; one __syncthreads; each warp ldmatrix's its
//   fragments and runs 48 mma.sync into fp32 register accumulators.
//   Double-buffered A/B; epilogue adds bias and stores D fragments.

namespace {
constexpr int B_ = 2, CIN_ = 64, COUT_ = 64, D_ = 8, H_ = 32, W_ = 32, K_ = 27;
constexpr int P_ = D_ * H_ * W_;              // 8192
constexpr int MTILE = 128;
constexpr int THREADS = 512;
constexpr int NBLK = (B_ * P_) / MTILE;       // 128

constexpr int SDb = H_ * W_ * CIN_ * 4;       // x byte strides (channels-last)
constexpr int SHb = W_ * CIN_ * 4;
constexpr int SWb = CIN_ * 4;

// dynamic smem: A [buf][hi16K|lo16K] then B [buf][hi8K|lo8K]
constexpr int SM_A = 0;
constexpr int SM_B = 2 * 32768;               // 65536
constexpr int SM_TOTAL = SM_B + 2 * 16384;    // 98304
constexpr unsigned FULL = 0xffffffffu;
}

__device__ __align__(256) float g_xT[B_ * P_ * CIN_];
__device__ __align__(256) unsigned char g_wB[K_ * 16384];   // [k][hi 8K | lo 8K]

// ---------------- helpers ----------------
__device__ __forceinline__ uint32_t smem_u32(const void* p) {
    uint32_t a;
    asm("{ .reg .u64 t; cvta.to.shared.u64 t, %1; cvt.u32.u64 %0, t; }"
        : "=r"(a) : "l"(p));
    return a;
}
__device__ __forceinline__ uint32_t bf16x2(float hi_elem, float lo_elem) {
    uint32_t r;
    asm("cvt.rn.bf16x2.f32 %0, %1, %2;" : "=r"(r) : "f"(hi_elem), "f"(lo_elem));
    return r;
}
__device__ __forceinline__ void ldm_x4(uint32_t* r, uint32_t addr) {
    asm volatile("ldmatrix.sync.aligned.m8n8.x4.shared.b16 {%0,%1,%2,%3}, [%4];"
                 : "=r"(r[0]), "=r"(r[1]), "=r"(r[2]), "=r"(r[3]) : "r"(addr));
}
__device__ __forceinline__ void mma_bf16(float* c, const uint32_t* a,
                                         const uint32_t* b) {
    asm volatile(
        "mma.sync.aligned.m16n8k16.row.col.f32.bf16.bf16.f32 "
        "{%0,%1,%2,%3}, {%4,%5,%6,%7}, {%8,%9}, {%0,%1,%2,%3};"
        : "+f"(c[0]), "+f"(c[1]), "+f"(c[2]), "+f"(c[3])
        : "r"(a[0]), "r"(a[1]), "r"(a[2]), "r"(a[3]), "r"(b[0]), "r"(b[1]));
}

// ---------------- prep ----------------
__global__ void prep_kernel(const float* __restrict__ x,
                            const float* __restrict__ w) {
    int stride = gridDim.x * blockDim.x;
    int tid = blockIdx.x * blockDim.x + threadIdx.x;
    // x [b][c][p] -> xT [b][p][c]
    for (int i = tid; i < B_ * CIN_ * P_; i += stride) {
        int s = i % P_;
        int c = (i / P_) % CIN_;
        int b = i / (P_ * CIN_);
        g_xT[(b * P_ + s) * CIN_ + c] = x[i];
    }
    // weight [o][c][k] -> per-k SW128-swizzled bf16 hi/lo images [o row 128B]
    for (int i = tid; i < K_ * COUT_ * CIN_; i += stride) {
        int c = i % CIN_;
        int o = (i / CIN_) % COUT_;
        int k = i / (CIN_ * COUT_);
        float v = w[(o * CIN_ + c) * K_ + k];
        __nv_bfloat16 hi = __float2bfloat16(v);
        __nv_bfloat16 lo = __float2bfloat16(v - __bfloat162float(hi));
        uint32_t off = (uint32_t)(o * 128 + c * 2);
        uint32_t sw = off ^ ((off >> 3) & 0x70);
        *reinterpret_cast<__nv_bfloat16*>(g_wB + (size_t)k * 16384 + sw) = hi;
        *reinterpret_cast<__nv_bfloat16*>(g_wB + (size_t)k * 16384 + 8192 + sw) = lo;
    }
}

// ---------------- main ----------------
__global__ __launch_bounds__(THREADS, 1)
void deform_hmma_kernel(const float* __restrict__ offset,
                        const float* __restrict__ bias,
                        float* __restrict__ out) {
    extern __shared__ __align__(1024) char smem[];
    const uint32_t sb = smem_u32(smem);

    const int tid  = threadIdx.x;
    const int lane = tid & 31;
    const int warp = tid >> 5;               // 16 warps
    const int blk  = blockIdx.x;
    const int b    = blk >> 6;
    const int p0   = (blk & 63) * MTILE;

    const float* offB = offset + (size_t)b * 3 * K_ * P_;
    const char*  xb   = reinterpret_cast<const char*>(g_xT + (size_t)b * P_ * CIN_);

    // sampling role
    const int half = lane >> 4;              // d-plane half
    const int c4   = lane & 15;              // float4 channel chunk
    const int pl_base = warp * 8;
    uint32_t wAoff[8];
#pragma unroll
    for (int i = 0; i < 8; i++) {
        int pl = pl_base + i;
        wAoff[i] = (uint32_t)(pl * 128 + ((c4 * 8) ^ ((pl & 7) << 4)));
    }

    // mma role: warp (mt, nt) owns D[mt*16..+15][nt*32..+31]
    const int mt = warp >> 1, nt = warp & 1;
    const int rowA = mt * 16 + (lane & 15);
    const uint32_t aBaseOff = (uint32_t)(rowA * 128);
    const uint32_t aXor = (uint32_t)((rowA & 7) << 4);
    const uint32_t aKh  = (uint32_t)((lane >> 4) << 4);    // +16B for k8..15
    const int rB0 = nt * 32 + (lane & 7) + ((lane >> 4) << 3);
    const uint32_t bXor = (uint32_t)((rB0 & 7) << 4);
    const uint32_t bKh  = (uint32_t)(((lane >> 3) & 1) << 4);

    float acc[4][4];
#pragma unroll
    for (int j = 0; j < 4; j++)
#pragma unroll
        for (int q = 0; q < 4; q++) acc[j][q] = 0.f;

#pragma unroll 1
    for (int k = 0; k < K_; k++) {
        const int buf = k & 1;
        char* AhP = smem + SM_A + buf * 32768;
        char* AlP = AhP + 16384;
        const uint32_t AhB = sb + SM_A + buf * 32768;
        const uint32_t AlB = AhB + 16384;
        const uint32_t BhB = sb + SM_B + buf * 16384;
        const uint32_t BlB = BhB + 8192;

        // stage pre-swizzled weight tile (16 KB)
        {
            const uint4* src = reinterpret_cast<const uint4*>(g_wB + (size_t)k * 16384);
            uint4* dst = reinterpret_cast<uint4*>(smem + SM_B + buf * 16384);
            dst[tid]       = __ldg(&src[tid]);
            dst[tid + 512] = __ldg(&src[tid + 512]);
        }

        // ---- sampling: 8 points per warp ----
        const int kd = k / 9, kh = (k / 3) % 3, kw = k % 3;
        const float* offk = offB + 3 * k * P_;

#pragma unroll
        for (int i = 0; i < 8; i++) {
            const int p  = p0 + pl_base + i;
            const int od = p >> 10, oh = (p >> 5) & 31, ow = p & 31;

            float zd = (float)(od - 1 + kd) + __ldg(offk + p);
            float zh = (float)(oh - 1 + kh) + __ldg(offk + P_ + p);
            float zw = (float)(ow - 1 + kw) + __ldg(offk + 2 * P_ + p);

            float fd = floorf(zd); int d0 = (int)fd; float rd = zd - fd;
            float fh = floorf(zh); int h0 = (int)fh; float rh = zh - fh;
            float fw = floorf(zw); int w0 = (int)fw; float rw = zw - fw;

            float wd0 = ((unsigned)d0       < (unsigned)D_) ? 1.f - rd : 0.f;
            float wd1 = ((unsigned)(d0 + 1) < (unsigned)D_) ? rd       : 0.f;
            float wh0 = ((unsigned)h0       < (unsigned)H_) ? 1.f - rh : 0.f;
            float wh1 = ((unsigned)(h0 + 1) < (unsigned)H_) ? rh       : 0.f;
            float ww0 = ((unsigned)w0       < (unsigned)W_) ? 1.f - rw : 0.f;
            float ww1 = ((unsigned)(w0 + 1) < (unsigned)W_) ? rw       : 0.f;

            int d0c = min(max(d0, 0), D_ - 1), d1c = min(max(d0 + 1, 0), D_ - 1);
            int h0c = min(max(h0, 0), H_ - 1), h1c = min(max(h0 + 1, 0), H_ - 1);
            int w0c = min(max(w0, 0), W_ - 1), w1c = min(max(w0 + 1, 0), W_ - 1);

            const float wd = half ? wd1 : wd0;
            const char* base2 = xb + (half ? d1c : d0c) * SDb + (c4 << 4);
            const int hw0 = h0c * SHb + w0c * SWb;
            const int hw1 = h0c * SHb + w1c * SWb;
            const int hw2 = h1c * SHb + w0c * SWb;
            const int hw3 = h1c * SHb + w1c * SWb;
            const float g0 = wd * (wh0 * ww0), g1 = wd * (wh0 * ww1);
            const float g2 = wd * (wh1 * ww0), g3 = wd * (wh1 * ww1);

            float4 v0 = __ldg(reinterpret_cast<const float4*>(base2 + hw0));
            float4 v1 = __ldg(reinterpret_cast<const float4*>(base2 + hw1));
            float4 v2 = __ldg(reinterpret_cast<const float4*>(base2 + hw2));
            float4 v3 = __ldg(reinterpret_cast<const float4*>(base2 + hw3));

            float ax = g0 * v0.x + g1 * v1.x + g2 * v2.x + g3 * v3.x;
            float ay = g0 * v0.y + g1 * v1.y + g2 * v2.y + g3 * v3.y;
            float az = g0 * v0.z + g1 * v1.z + g2 * v2.z + g3 * v3.z;
            float aw = g0 * v0.w + g1 * v1.w + g2 * v2.w + g3 * v3.w;

            ax += __shfl_down_sync(FULL, ax, 16);
            ay += __shfl_down_sync(FULL, ay, 16);
            az += __shfl_down_sync(FULL, az, 16);
            aw += __shfl_down_sync(FULL, aw, 16);

            if (half == 0) {
                uint32_t h01 = bf16x2(ay, ax);       // hi=ch+1, lo=ch+0
                uint32_t h23 = bf16x2(aw, az);
                float hx = __uint_as_float(h01 << 16);
                float hy = __uint_as_float(h01 & 0xffff0000u);
                float hz = __uint_as_float(h23 << 16);
                float hww = __uint_as_float(h23 & 0xffff0000u);
                uint32_t l01 = bf16x2(ay - hy, ax - hx);
                uint32_t l23 = bf16x2(aw - hww, az - hz);
                *reinterpret_cast<uint2*>(AhP + wAoff[i]) = make_uint2(h01, h23);
                *reinterpret_cast<uint2*>(AlP + wAoff[i]) = make_uint2(l01, l23);
            }
        }

        __syncthreads();

        // ---- HMMA: 4 K-steps, hi/lo 3-term, 4 n-tiles ----
#pragma unroll
        for (int ks = 0; ks < 4; ks++) {
            const uint32_t kb = (uint32_t)(ks * 32);
            uint32_t ah[4], al[4];
            const uint32_t aoff = aBaseOff + ((kb + aKh) ^ aXor);
            ldm_x4(ah, AhB + aoff);
            ldm_x4(al, AlB + aoff);

            uint32_t bh[2][4], bl[2][4];
#pragma unroll
            for (int pr = 0; pr < 2; pr++) {
                const uint32_t boff =
                    (uint32_t)((rB0 + pr * 16) * 128) + ((kb + bKh) ^ bXor);
                ldm_x4(bh[pr], BhB + boff);
                ldm_x4(bl[pr], BlB + boff);
            }
#pragma unroll
            for (int j = 0; j < 4; j++) {
                const int pr = j >> 1, sub = (j & 1) * 2;
                mma_bf16(acc[j], ah, &bh[pr][sub]);
                mma_bf16(acc[j], al, &bh[pr][sub]);
                mma_bf16(acc[j], ah, &bl[pr][sub]);
            }
        }
        // no second barrier: buf reused only at k+2, ordered by sync(k+1)
    }

    // ---- epilogue: D fragment scatter + bias ----
    const int m = lane >> 2;
    const int p = p0 + mt * 16 + m;
#pragma unroll
    for (int j = 0; j < 4; j++) {
        const int n = nt * 32 + j * 8 + 2 * (lane & 3);
        const float bv0 = __ldg(&bias[n]);
        const float bv1 = __ldg(&bias[n + 1]);
        float* o0 = out + ((size_t)(b * COUT_ + n)) * P_ + p;
        o0[0]      = acc[j][0] + bv0;   // (m,   n)
        o0[P_]     = acc[j][1] + bv1;   // (m,   n+1)
        o0[8]      = acc[j][2] + bv0;   // (m+8, n)
        o0[P_ + 8] = acc[j][3] + bv1;   // (m+8, n+1)
    }
}

extern "C" void kernel_launch(void* const* d_in, const int* in_sizes, int n_in,
                              void* d_out, int out_size) {
    const float* x      = (const float*)d_in[0];
    const float* offset = (const float*)d_in[1];
    const float* weight = (const float*)d_in[2];
    const float* bias   = (const float*)d_in[3];
    float* out = (float*)d_out;

    cudaFuncSetAttribute(deform_hmma_kernel,
                         cudaFuncAttributeMaxDynamicSharedMemorySize, SM_TOTAL);
    prep_kernel<<<256, 256>>>(x, weight);
    deform_hmma_kernel<<<NBLK, THREADS, SM_TOTAL>>>(offset, bias, out);
}